// round 15
// baseline (speedup 1.0000x reference)
#include <cuda_runtime.h>
#include <cstdint>

#define DD 128
#define GG 384
#define BV 256
#define MM 32
#define LL 24
#define NOUT 193

// ---------------- scratch (static device globals; no allocation) -------------
__device__ float g_xg34[2 * BV * MM * GG];     // monitor input-gates, keys 3,4
__device__ float g_xg012[3 * BV * GG];         // monitor input-gates, keys 0-2 (t-invariant)
__device__ float g_h5[5 * BV * DD];            // monitor final hidden
__device__ float g_hv[7 * 16 * DD];            // visit final hidden
__device__ float g_wT[24 * DD * GG];           // transposed weights [d][g] (slices 0-2,10-23)
__device__ uint2 g_wB34[2 * 48 * 16 * 32];     // tf32 B fragments: mgru_wih keys 3,4
__device__ uint2 g_wBhh[5 * 48 * 16 * 32];     // tf32 B fragments: mgru_whh keys 0..4

#define WIH_M 0
#define WIH_V (10 * DD * GG)
#define WHH_V (17 * DD * GG)

__device__ __forceinline__ float sigf(float x) { return 1.0f / (1.0f + __expf(-x)); }
__device__ __forceinline__ float tanhf_fast(float x) {
    return 1.0f - __fdividef(2.0f, __expf(2.0f * x) + 1.0f);
}

__device__ __forceinline__ uint32_t f2tf32(float x) {
    uint32_t u; asm("cvt.rna.tf32.f32 %0, %1;" : "=r"(u) : "f"(x)); return u;
}
__device__ __forceinline__ void mma_tf32(float* c, const uint32_t* a, uint2 b) {
    asm volatile("mma.sync.aligned.m16n8k8.row.col.f32.tf32.tf32.f32 "
                 "{%0,%1,%2,%3}, {%4,%5,%6,%7}, {%8,%9}, {%0,%1,%2,%3};"
                 : "+f"(c[0]), "+f"(c[1]), "+f"(c[2]), "+f"(c[3])
                 : "r"(a[0]), "r"(a[1]), "r"(a[2]), "r"(a[3]), "r"(b.x), "r"(b.y));
}

// ---------------- K_prep: fused weight transpose + tf32 fragment packs --------
__global__ void __launch_bounds__(256) k_prep(const float* __restrict__ mih,
                                              const float* __restrict__ mhh,
                                              const float* __restrict__ vih,
                                              const float* __restrict__ vhh) {
    int b = blockIdx.x, tid = threadIdx.x;
    if (b < 3264) {
        int i = b * 256 + tid;          // < 835584
        int yy = i / 49152;             // 0..16
        int r  = i % 49152;             // d*384+g
        int d = r / GG, g = r % GG;
        const float* src; int k, slice;
        if (yy < 3)       { src = mih; k = yy;      slice = yy; }
        else if (yy < 10) { src = vih; k = yy - 3;  slice = 10 + (yy - 3); }
        else              { src = vhh; k = yy - 10; slice = 17 + (yy - 10); }
        g_wT[slice * 49152 + r] = src[(k * GG + g) * DD + d];
    } else if (b < 3456) {
        int idx = (b - 3264) * 256 + tid;   // < 49152
        int lane = idx & 31;
        int ks = (idx >> 5) & 15;
        int tmp = idx >> 9;
        int pair = tmp / 48, nt = tmp % 48;
        int n = nt * 8 + (lane >> 2);
        int k = ks * 8 + (lane & 3);
        const float* W = mih + (3 + pair) * (GG * DD);
        uint2 o;
        o.x = f2tf32(W[n * DD + k]);
        o.y = f2tf32(W[n * DD + k + 4]);
        g_wB34[idx] = o;
    } else {
        int idx = (b - 3456) * 256 + tid;   // < 122880
        int lane = idx & 31;
        int ks = (idx >> 5) & 15;
        int tmp = idx >> 9;
        int key = tmp / 48, nt = tmp % 48;
        int n = nt * 8 + (lane >> 2);
        int k = ks * 8 + (lane & 3);
        const float* W = mhh + key * (GG * DD);
        uint2 o;
        o.x = f2tf32(W[n * DD + k]);
        o.y = f2tf32(W[n * DD + k + 4]);
        g_wBhh[idx] = o;
    }
}

// ---------------- K3a: FUSED monitor embedding + input-gates keys 3,4 ---------
// grid (128, 2), block 512 (16 warps, 3 n-tiles each), 2 sequences per CTA.
// Phase 1: gather pair embeddings directly into sX (no g_mon roundtrip).
// Phase 2: tf32 mma, B fragments loaded once per ks, reused across 4 m-tiles.
__global__ void __launch_bounds__(512, 1) k_xg34_mma(
        const int* __restrict__ tli, const int* __restrict__ tlv,
        const int* __restrict__ tii, const int* __restrict__ tiv,
        const float* __restrict__ eli, const float* __restrict__ elv,
        const float* __restrict__ eii, const float* __restrict__ eiv,
        const float* __restrict__ bih) {
    __shared__ float sX[2 * 32 * 132];
    int pair = blockIdx.y, bx = blockIdx.x, key = 3 + pair;
    int n0 = bx * 2;
    int tid = threadIdx.x, lane = tid & 31, wid = tid >> 5;   // wid 0..15
    // phase 1: gather 64 rows (2 seq x 32 monitors), one warp per row
    {
        const int* ti = pair ? tii : tli;
        const int* tv = pair ? tiv : tlv;
        const float4* ei = (const float4*)(pair ? eii : eli);
        const float4* ev = (const float4*)(pair ? eiv : elv);
        for (int rr = wid; rr < 64; rr += 16) {
            int s = rr >> 5, t = rr & 31;
            long row = (long)(n0 + s) * MM + t;
            const int* tip = ti + row * LL;
            const int* tvp = tv + row * LL;
            float4 acc = make_float4(0.f, 0.f, 0.f, 0.f);
#pragma unroll
            for (int l = 0; l < LL; l++) {
                int a = tip[l];
                int b = tvp[l];
                float4 x = ei[a * 32 + lane];
                float4 y = ev[b * 32 + lane];
                acc.x += x.x * y.x; acc.y += x.y * y.y;
                acc.z += x.z * y.z; acc.w += x.w * y.w;
            }
            *(float4*)&sX[rr * 132 + lane * 4] = acc;
        }
    }
    __syncthreads();
    // phase 2: mma
    int r = lane >> 2, cc = lane & 3;
    float c[2][2][3][4];                        // [seq][mt][j][q]
#pragma unroll
    for (int s = 0; s < 2; s++)
#pragma unroll
        for (int m = 0; m < 2; m++)
#pragma unroll
            for (int j = 0; j < 3; j++)
#pragma unroll
                for (int q = 0; q < 4; q++) c[s][m][j][q] = 0.f;
    const uint2* Bbase = &g_wB34[((pair * 48 + wid * 3) * 16) * 32 + lane];
#pragma unroll 2
    for (int ks = 0; ks < 16; ks++) {
        int k0 = ks * 8;
        uint2 B[3];
#pragma unroll
        for (int j = 0; j < 3; j++) B[j] = Bbase[(j * 16 + ks) * 32];
#pragma unroll
        for (int s = 0; s < 2; s++) {
#pragma unroll
            for (int m = 0; m < 2; m++) {
                int row = s * 32 + m * 16 + r;
                uint32_t A[4];
                A[0] = f2tf32(sX[row * 132 + k0 + cc]);
                A[1] = f2tf32(sX[(row + 8) * 132 + k0 + cc]);
                A[2] = f2tf32(sX[row * 132 + k0 + cc + 4]);
                A[3] = f2tf32(sX[(row + 8) * 132 + k0 + cc + 4]);
#pragma unroll
                for (int j = 0; j < 3; j++) mma_tf32(c[s][m][j], A, B[j]);
            }
        }
    }
#pragma unroll
    for (int s = 0; s < 2; s++) {
        float* outbase = &g_xg34[((pair * BV + n0 + s) * MM) * GG];
#pragma unroll
        for (int j = 0; j < 3; j++) {
            int col = wid * 24 + j * 8 + 2 * cc;
            float2 bias = *(const float2*)&bih[key * GG + col];
#pragma unroll
            for (int m = 0; m < 2; m++) {
                int row0 = m * 16 + r;
                float2 v0 = make_float2(c[s][m][j][0] + bias.x, c[s][m][j][1] + bias.y);
                float2 v1 = make_float2(c[s][m][j][2] + bias.x, c[s][m][j][3] + bias.y);
                *(float2*)&outbase[row0 * GG + col] = v0;
                *(float2*)&outbase[(row0 + 8) * GG + col] = v1;
            }
        }
    }
}

// ---------------- K3b: fused visit-embedding + input-gates keys 0-2 -----------
__global__ void __launch_bounds__(384) k_embed_xg012(
        const int* __restrict__ tc, const int* __restrict__ tp, const int* __restrict__ td,
        const float* __restrict__ ec, const float* __restrict__ ep, const float* __restrict__ ed,
        const float* __restrict__ bih) {
    __shared__ float sx[DD];
    int key = blockIdx.y, n = blockIdx.x, g = threadIdx.x;
    if (g < DD) {
        const int* tok = (key == 0) ? tc : (key == 1) ? tp : td;
        const float* emb = (key == 0) ? ec : (key == 1) ? ep : ed;
        float acc = 0.f;
#pragma unroll
        for (int l = 0; l < LL; l++) acc += emb[tok[n * LL + l] * DD + g];
        sx[g] = acc;
    }
    __syncthreads();
    float acc = bih[key * GG + g];
    const float* w = &g_wT[WIH_M + key * (DD * GG) + g];
#pragma unroll 4
    for (int d = 0; d < DD; d++) acc += w[d * GG] * sx[d];
    g_xg012[(key * BV + n) * GG + g] = acc;
}

// ---------------- K4: monitor GRU recurrence — tf32 mma, 16 warps -------------
// grid (16, 5), block 512 (16 warps, 3 n-tiles each), dyn smem = 230144 B
__global__ void __launch_bounds__(512, 1) k_mon_gru(const float* __restrict__ bhh) {
    extern __shared__ float sm[];
    uint2* s_wB = (uint2*)sm;                 // 196608 B
    float* s_h  = sm + 49152;                 // 16*132 floats
    float* s_gh = sm + 49152 + 16 * 132;      // 16*392 floats
    int key = blockIdx.y, grp = blockIdx.x;
    int tid = threadIdx.x, lane = tid & 31, wid = tid >> 5;   // wid 0..15
    int n0 = grp * 16;
    {
        const float4* src = (const float4*)(g_wBhh + key * 24576);
        float4* dst = (float4*)s_wB;
        for (int i = tid; i < 12288; i += 512) dst[i] = src[i];
    }
    for (int i = tid; i < 16 * 132; i += 512) s_h[i] = 0.f;
    __syncthreads();

    // gate-phase mapping: thread owns 4 (s,d) pairs: s = sblk + 4p, d = dd
    int sblk = tid >> 7, dd = tid & 127;      // sblk 0..3
    float br = bhh[key * GG + dd];
    float bz = bhh[key * GG + DD + dd];
    float bn = bhh[key * GG + 2 * DD + dd];
    float xr[4], xz[4], xn[4];
    const float* xgp[4];
#pragma unroll
    for (int p = 0; p < 4; p++) {
        int n = n0 + sblk + p * 4;
        if (key < 3) {
            const float* xg = &g_xg012[(key * BV + n) * GG];
            xr[p] = xg[dd]; xz[p] = xg[DD + dd]; xn[p] = xg[2 * DD + dd];
            xgp[p] = nullptr;
        } else {
            xgp[p] = &g_xg34[(((key - 3) * BV + n) * MM) * GG];
        }
    }

    int r = lane >> 2, cc = lane & 3;
    const uint2* Bb = s_wB + (wid * 3 * 16) * 32 + lane;   // 3 j-tiles per warp

    for (int t = 0; t < MM; t++) {
        if (key >= 3) {
#pragma unroll
            for (int p = 0; p < 4; p++) {
                const float* xg = xgp[p] + t * GG;
                xr[p] = __ldg(xg + dd);
                xz[p] = __ldg(xg + DD + dd);
                xn[p] = __ldg(xg + 2 * DD + dd);
            }
        }
        float c[3][4];
#pragma unroll
        for (int j = 0; j < 3; j++)
#pragma unroll
            for (int q = 0; q < 4; q++) c[j][q] = 0.f;
#pragma unroll 4
        for (int ks = 0; ks < 16; ks++) {
            int k0 = ks * 8;
            uint32_t A[4];
            A[0] = f2tf32(s_h[r * 132 + k0 + cc]);
            A[1] = f2tf32(s_h[(r + 8) * 132 + k0 + cc]);
            A[2] = f2tf32(s_h[r * 132 + k0 + cc + 4]);
            A[3] = f2tf32(s_h[(r + 8) * 132 + k0 + cc + 4]);
#pragma unroll
            for (int j = 0; j < 3; j++) {
                uint2 b = Bb[(j * 16 + ks) * 32];
                mma_tf32(c[j], A, b);
            }
        }
#pragma unroll
        for (int j = 0; j < 3; j++) {
            int col = wid * 24 + j * 8 + 2 * cc;
            *(float2*)&s_gh[r * 392 + col] = make_float2(c[j][0], c[j][1]);
            *(float2*)&s_gh[(r + 8) * 392 + col] = make_float2(c[j][2], c[j][3]);
        }
        __syncthreads();
#pragma unroll
        for (int p = 0; p < 4; p++) {
            int s = sblk + p * 4;
            float ghr = s_gh[s * 392 + dd];
            float ghz = s_gh[s * 392 + DD + dd];
            float ghn = s_gh[s * 392 + 2 * DD + dd];
            float h = s_h[s * 132 + dd];
            float rr = sigf(xr[p] + ghr + br);
            float zz = sigf(xz[p] + ghz + bz);
            float nn = tanhf_fast(xn[p] + rr * (ghn + bn));
            s_h[s * 132 + dd] = (1.f - zz) * nn + zz * h;
        }
        __syncthreads();
    }
    for (int i = tid; i < 16 * DD; i += 512) {
        int s = i >> 7, d = i & 127;
        g_h5[(key * BV + n0 + s) * DD + d] = s_h[s * 132 + d];
    }
}

// ---------------- K5+K6 fused: visit input-gates + visit GRU recurrence -------
__global__ void __launch_bounds__(384) k_vxg_vis(
        const float* __restrict__ weight, const float* __restrict__ age,
        const float* __restrict__ info_w, const float* __restrict__ info_b,
        const float* __restrict__ bih, const float* __restrict__ bhh) {
    extern __shared__ float sm[];
    float* s_w  = sm;                   // 49152
    float* s_xg = sm + 49152;           // 6208
    float* s_h  = s_xg + 6208;          // 128
    float* s_gh = s_h + 128;            // 384
    float* sx   = s_xg;                 // alias (2048 floats) during phase 1-2
    int key = blockIdx.y, b = blockIdx.x, g = threadIdx.x;
    // phase 1: gather x [16][128]
    for (int i = g; i < 16 * DD; i += GG) {
        int v = i / DD, d = i % DD;
        float x;
        if (key < 5)       x = g_h5[(key * BV + b * 16 + v) * DD + d];
        else if (key == 5) x = weight[b * 16 + v] * info_w[d] + info_b[d];
        else               x = age[b * 16 + v] * info_w[DD + d] + info_b[DD + d];
        sx[i] = x;
    }
    __syncthreads();
    // phase 2: input-gate dot (Wih_v streamed from L2)
    float bb = bih[key * GG + g];
    float acc[16];
#pragma unroll
    for (int v = 0; v < 16; v++) acc[v] = bb;
    {
        const float* w = &g_wT[WIH_V + key * (DD * GG) + g];
        for (int d = 0; d < DD; d++) {
            float wv = w[d * GG];
#pragma unroll
            for (int v = 0; v < 16; v++) acc[v] += wv * sx[v * DD + d];
        }
    }
    __syncthreads();
    // phase 3: stage gates to smem; load Whh_v; init h
#pragma unroll
    for (int v = 0; v < 16; v++) s_xg[v * 388 + g] = acc[v];
    {
        const float4* src = (const float4*)&g_wT[WHH_V + key * (DD * GG)];
        float4* dst = (float4*)s_w;
        for (int i = g; i < 12288; i += GG) dst[i] = src[i];
    }
    if (g < DD) s_h[g] = 0.f;
    float bh = bhh[key * GG + g];
    __syncthreads();
    // phase 4: 16-step recurrence
    for (int t = 0; t < 16; t++) {
        float a = bh;
#pragma unroll 4
        for (int d = 0; d < DD; d++) a += s_w[d * GG + g] * s_h[d];
        s_gh[g] = a;
        __syncthreads();
        if (g < DD) {
            const float* xg = &s_xg[t * 388];
            float r = sigf(xg[g] + s_gh[g]);
            float z = sigf(xg[DD + g] + s_gh[DD + g]);
            float nn = tanhf_fast(xg[2 * DD + g] + r * s_gh[2 * DD + g]);
            s_h[g] = (1.f - z) * nn + z * s_h[g];
        }
        __syncthreads();
    }
    if (g < DD) g_hv[(key * 16 + b) * DD + g] = s_h[g];
}

// ---------------- K7: ReLU + final FC --------------------------------------------
__global__ void k_fc(const float* fcw, const float* fcb, float* out) {
    __shared__ float pe[7 * DD];
    int b = blockIdx.x, o = threadIdx.x;
    for (int i = o; i < 7 * DD; i += 256) {
        int k = i / DD, d = i % DD;
        pe[i] = fmaxf(g_hv[(k * 16 + b) * DD + d], 0.f);
    }
    __syncthreads();
    if (o < NOUT) {
        float acc = fcb[o];
        for (int j = 0; j < 7 * DD; j++) acc += pe[j] * fcw[j * NOUT + o];
        out[b * NOUT + o] = acc;
    }
}

// ---------------- launch -----------------------------------------------------------
extern "C" void kernel_launch(void* const* d_in, const int* in_sizes, int n_in,
                              void* d_out, int out_size) {
    const int* tok_cond      = (const int*)d_in[0];
    const int* tok_proc      = (const int*)d_in[1];
    const int* tok_drug      = (const int*)d_in[2];
    const int* tok_lab_item  = (const int*)d_in[3];
    const int* tok_lab_value = (const int*)d_in[4];
    const int* tok_inj_item  = (const int*)d_in[5];
    const int* tok_inj_value = (const int*)d_in[6];
    const float* weight      = (const float*)d_in[7];
    const float* age         = (const float*)d_in[8];
    const float* emb_cond    = (const float*)d_in[9];
    const float* emb_proc    = (const float*)d_in[10];
    const float* emb_drug    = (const float*)d_in[11];
    const float* emb_li      = (const float*)d_in[12];
    const float* emb_lv      = (const float*)d_in[13];
    const float* emb_ii      = (const float*)d_in[14];
    const float* emb_iv      = (const float*)d_in[15];
    const float* mgru_wih    = (const float*)d_in[16];
    const float* mgru_whh    = (const float*)d_in[17];
    const float* mgru_bih    = (const float*)d_in[18];
    const float* mgru_bhh    = (const float*)d_in[19];
    const float* vgru_wih    = (const float*)d_in[20];
    const float* vgru_whh    = (const float*)d_in[21];
    const float* vgru_bih    = (const float*)d_in[22];
    const float* vgru_bhh    = (const float*)d_in[23];
    const float* info_w      = (const float*)d_in[24];
    const float* info_b      = (const float*)d_in[25];
    const float* fc_w        = (const float*)d_in[26];
    const float* fc_b        = (const float*)d_in[27];
    float* out = (float*)d_out;

    cudaFuncSetAttribute(k_mon_gru, cudaFuncAttributeMaxDynamicSharedMemorySize, 230144);
    cudaFuncSetAttribute(k_vxg_vis, cudaFuncAttributeMaxDynamicSharedMemorySize, 223488);

    // Streams/events created ONCE on the first call (before the harness's
    // pre-capture baseline) and reused forever; nothing created/destroyed
    // during capture/replay.
    static cudaStream_t sA = nullptr, sB = nullptr;
    static cudaEvent_t eF = nullptr, eA = nullptr, eB = nullptr;
    if (sA == nullptr) {
        cudaStreamCreateWithFlags(&sA, cudaStreamNonBlocking);
        cudaStreamCreateWithFlags(&sB, cudaStreamNonBlocking);
        cudaEventCreateWithFlags(&eF, cudaEventDisableTiming);
        cudaEventCreateWithFlags(&eA, cudaEventDisableTiming);
        cudaEventCreateWithFlags(&eB, cudaEventDisableTiming);
    }

    cudaEventRecord(eF, 0);
    cudaStreamWaitEvent(sA, eF, 0);

    // stream A: weight prep (transpose + tf32 packs)
    k_prep<<<3936, 256, 0, sA>>>(mgru_wih, mgru_whh, vgru_wih, vgru_whh);
    cudaEventRecord(eA, sA);

    // stream B: visit embeddings + xg for keys 0-2 (needs transposed WIH_M)
    cudaStreamWaitEvent(sB, eA, 0);
    k_embed_xg012<<<dim3(256, 3), 384, 0, sB>>>(tok_cond, tok_proc, tok_drug,
                                                emb_cond, emb_proc, emb_drug, mgru_bih);
    cudaEventRecord(eB, sB);

    // main stream: fused embed+xg34 -> mon_gru -> visit -> fc
    cudaStreamWaitEvent(0, eA, 0);
    k_xg34_mma<<<dim3(128, 2), 512>>>(tok_lab_item, tok_lab_value,
                                      tok_inj_item, tok_inj_value,
                                      emb_li, emb_lv, emb_ii, emb_iv, mgru_bih);
    cudaStreamWaitEvent(0, eB, 0);
    k_mon_gru<<<dim3(16, 5), 512, 230144>>>(mgru_bhh);
    k_vxg_vis<<<dim3(16, 7), 384, 223488>>>(weight, age, info_w, info_b,
                                            vgru_bih, vgru_bhh);
    k_fc<<<16, 256>>>(fc_w, fc_b, out);
}

// round 16
// speedup vs baseline: 1.0294x; 1.0294x over previous
#include <cuda_runtime.h>
#include <cstdint>

#define DD 128
#define GG 384
#define BV 256
#define MM 32
#define LL 24
#define NOUT 193

// ---------------- scratch (static device globals; no allocation) -------------
__device__ float g_xg34[2 * BV * MM * GG];     // monitor input-gates, keys 3,4
__device__ float g_xg012[3 * BV * GG];         // monitor input-gates, keys 0-2 (t-invariant)
__device__ float g_h5[5 * BV * DD];            // monitor final hidden
__device__ float g_hv[7 * 16 * DD];            // visit final hidden
__device__ float g_wT[24 * DD * GG];           // transposed weights [d][g] (slices 0-2,10-23)
__device__ uint2 g_wB34[2 * 48 * 16 * 32];     // tf32 B fragments: mgru_wih keys 3,4
__device__ uint2 g_wBhh[5 * 48 * 16 * 32];     // tf32 B fragments: mgru_whh keys 0..4

#define WIH_M 0
#define WIH_V (10 * DD * GG)
#define WHH_V (17 * DD * GG)

__device__ __forceinline__ float sigf(float x) { return 1.0f / (1.0f + __expf(-x)); }
__device__ __forceinline__ float tanhf_fast(float x) {
    return 1.0f - __fdividef(2.0f, __expf(2.0f * x) + 1.0f);
}

__device__ __forceinline__ uint32_t f2tf32(float x) {
    uint32_t u; asm("cvt.rna.tf32.f32 %0, %1;" : "=r"(u) : "f"(x)); return u;
}
__device__ __forceinline__ void mma_tf32(float* c, const uint32_t* a, uint2 b) {
    asm volatile("mma.sync.aligned.m16n8k8.row.col.f32.tf32.tf32.f32 "
                 "{%0,%1,%2,%3}, {%4,%5,%6,%7}, {%8,%9}, {%0,%1,%2,%3};"
                 : "+f"(c[0]), "+f"(c[1]), "+f"(c[2]), "+f"(c[3])
                 : "r"(a[0]), "r"(a[1]), "r"(a[2]), "r"(a[3]), "r"(b.x), "r"(b.y));
}

// ---------------- K_prep: fused weight transpose + tf32 fragment packs --------
__global__ void __launch_bounds__(256) k_prep(const float* __restrict__ mih,
                                              const float* __restrict__ mhh,
                                              const float* __restrict__ vih,
                                              const float* __restrict__ vhh) {
    int b = blockIdx.x, tid = threadIdx.x;
    if (b < 3264) {
        int i = b * 256 + tid;          // < 835584
        int yy = i / 49152;             // 0..16
        int r  = i % 49152;             // d*384+g
        int d = r / GG, g = r % GG;
        const float* src; int k, slice;
        if (yy < 3)       { src = mih; k = yy;      slice = yy; }
        else if (yy < 10) { src = vih; k = yy - 3;  slice = 10 + (yy - 3); }
        else              { src = vhh; k = yy - 10; slice = 17 + (yy - 10); }
        g_wT[slice * 49152 + r] = src[(k * GG + g) * DD + d];
    } else if (b < 3456) {
        int idx = (b - 3264) * 256 + tid;   // < 49152
        int lane = idx & 31;
        int ks = (idx >> 5) & 15;
        int tmp = idx >> 9;
        int pair = tmp / 48, nt = tmp % 48;
        int n = nt * 8 + (lane >> 2);
        int k = ks * 8 + (lane & 3);
        const float* W = mih + (3 + pair) * (GG * DD);
        uint2 o;
        o.x = f2tf32(W[n * DD + k]);
        o.y = f2tf32(W[n * DD + k + 4]);
        g_wB34[idx] = o;
    } else {
        int idx = (b - 3456) * 256 + tid;   // < 122880
        int lane = idx & 31;
        int ks = (idx >> 5) & 15;
        int tmp = idx >> 9;
        int key = tmp / 48, nt = tmp % 48;
        int n = nt * 8 + (lane >> 2);
        int k = ks * 8 + (lane & 3);
        const float* W = mhh + key * (GG * DD);
        uint2 o;
        o.x = f2tf32(W[n * DD + k]);
        o.y = f2tf32(W[n * DD + k + 4]);
        g_wBhh[idx] = o;
    }
}

// ---------------- K3a: FUSED monitor embedding + input-gates keys 3,4 ---------
__global__ void __launch_bounds__(512, 1) k_xg34_mma(
        const int* __restrict__ tli, const int* __restrict__ tlv,
        const int* __restrict__ tii, const int* __restrict__ tiv,
        const float* __restrict__ eli, const float* __restrict__ elv,
        const float* __restrict__ eii, const float* __restrict__ eiv,
        const float* __restrict__ bih) {
    __shared__ float sX[2 * 32 * 132];
    int pair = blockIdx.y, bx = blockIdx.x, key = 3 + pair;
    int n0 = bx * 2;
    int tid = threadIdx.x, lane = tid & 31, wid = tid >> 5;   // wid 0..15
    // phase 1: gather 64 rows (2 seq x 32 monitors), one warp per row
    {
        const int* ti = pair ? tii : tli;
        const int* tv = pair ? tiv : tlv;
        const float4* ei = (const float4*)(pair ? eii : eli);
        const float4* ev = (const float4*)(pair ? eiv : elv);
        for (int rr = wid; rr < 64; rr += 16) {
            int s = rr >> 5, t = rr & 31;
            long row = (long)(n0 + s) * MM + t;
            const int* tip = ti + row * LL;
            const int* tvp = tv + row * LL;
            float4 acc = make_float4(0.f, 0.f, 0.f, 0.f);
#pragma unroll
            for (int l = 0; l < LL; l++) {
                int a = tip[l];
                int b = tvp[l];
                float4 x = ei[a * 32 + lane];
                float4 y = ev[b * 32 + lane];
                acc.x += x.x * y.x; acc.y += x.y * y.y;
                acc.z += x.z * y.z; acc.w += x.w * y.w;
            }
            *(float4*)&sX[rr * 132 + lane * 4] = acc;
        }
    }
    __syncthreads();
    // phase 2: mma
    int r = lane >> 2, cc = lane & 3;
    float c[2][2][3][4];                        // [seq][mt][j][q]
#pragma unroll
    for (int s = 0; s < 2; s++)
#pragma unroll
        for (int m = 0; m < 2; m++)
#pragma unroll
            for (int j = 0; j < 3; j++)
#pragma unroll
                for (int q = 0; q < 4; q++) c[s][m][j][q] = 0.f;
    const uint2* Bbase = &g_wB34[((pair * 48 + wid * 3) * 16) * 32 + lane];
#pragma unroll 2
    for (int ks = 0; ks < 16; ks++) {
        int k0 = ks * 8;
        uint2 B[3];
#pragma unroll
        for (int j = 0; j < 3; j++) B[j] = Bbase[(j * 16 + ks) * 32];
#pragma unroll
        for (int s = 0; s < 2; s++) {
#pragma unroll
            for (int m = 0; m < 2; m++) {
                int row = s * 32 + m * 16 + r;
                uint32_t A[4];
                A[0] = f2tf32(sX[row * 132 + k0 + cc]);
                A[1] = f2tf32(sX[(row + 8) * 132 + k0 + cc]);
                A[2] = f2tf32(sX[row * 132 + k0 + cc + 4]);
                A[3] = f2tf32(sX[(row + 8) * 132 + k0 + cc + 4]);
#pragma unroll
                for (int j = 0; j < 3; j++) mma_tf32(c[s][m][j], A, B[j]);
            }
        }
    }
#pragma unroll
    for (int s = 0; s < 2; s++) {
        float* outbase = &g_xg34[((pair * BV + n0 + s) * MM) * GG];
#pragma unroll
        for (int j = 0; j < 3; j++) {
            int col = wid * 24 + j * 8 + 2 * cc;
            float2 bias = *(const float2*)&bih[key * GG + col];
#pragma unroll
            for (int m = 0; m < 2; m++) {
                int row0 = m * 16 + r;
                float2 v0 = make_float2(c[s][m][j][0] + bias.x, c[s][m][j][1] + bias.y);
                float2 v1 = make_float2(c[s][m][j][2] + bias.x, c[s][m][j][3] + bias.y);
                *(float2*)&outbase[row0 * GG + col] = v0;
                *(float2*)&outbase[(row0 + 8) * GG + col] = v1;
            }
        }
    }
}

// ---------------- K3b: fused visit-embedding + input-gates keys 0-2 -----------
__global__ void __launch_bounds__(384) k_embed_xg012(
        const int* __restrict__ tc, const int* __restrict__ tp, const int* __restrict__ td,
        const float* __restrict__ ec, const float* __restrict__ ep, const float* __restrict__ ed,
        const float* __restrict__ bih) {
    __shared__ float sx[DD];
    int key = blockIdx.y, n = blockIdx.x, g = threadIdx.x;
    if (g < DD) {
        const int* tok = (key == 0) ? tc : (key == 1) ? tp : td;
        const float* emb = (key == 0) ? ec : (key == 1) ? ep : ed;
        float acc = 0.f;
#pragma unroll
        for (int l = 0; l < LL; l++) acc += emb[tok[n * LL + l] * DD + g];
        sx[g] = acc;
    }
    __syncthreads();
    float acc = bih[key * GG + g];
    const float* w = &g_wT[WIH_M + key * (DD * GG) + g];
#pragma unroll 4
    for (int d = 0; d < DD; d++) acc += w[d * GG] * sx[d];
    g_xg012[(key * BV + n) * GG + g] = acc;
}

// ---------------- K4: monitor GRU — h as tf32 A-fragments in smem -------------
// grid (16, 5), block 512 (16 warps, 3 n-tiles each), dyn smem = 229888 B
//   s_wB : 24576 uint2 (196608 B)    Whh tf32 B fragments
//   s_hc : 16 ks x 128 uint32 (8192 B)  h as tf32 A fragments (fragment-native)
//   s_gh : 16 x 392 fp32 (25088 B)   gh staging
// h itself lives in 4 registers per thread (gate thread owns its (s,d) pairs).
__global__ void __launch_bounds__(512, 1) k_mon_gru(const float* __restrict__ bhh) {
    extern __shared__ float sm[];
    uint2* s_wB = (uint2*)sm;                       // 196608 B
    uint32_t* s_hc = (uint32_t*)(sm + 49152);       // 2048 words
    float* s_gh = sm + 49152 + 2048;                // 16*392 floats
    int key = blockIdx.y, grp = blockIdx.x;
    int tid = threadIdx.x, lane = tid & 31, wid = tid >> 5;   // wid 0..15
    int n0 = grp * 16;
    {
        const float4* src = (const float4*)(g_wBhh + key * 24576);
        float4* dst = (float4*)s_wB;
        for (int i = tid; i < 12288; i += 512) dst[i] = src[i];
    }
    for (int i = tid; i < 2048; i += 512) s_hc[i] = 0u;   // tf32(0) == 0
    __syncthreads();

    // gate-phase mapping: thread owns 4 (s,d) pairs: s = sblk + 4p, d = dd
    int sblk = tid >> 7, dd = tid & 127;      // sblk 0..3
    float br = bhh[key * GG + dd];
    float bz = bhh[key * GG + DD + dd];
    float bn = bhh[key * GG + 2 * DD + dd];
    float h[4] = {0.f, 0.f, 0.f, 0.f};
    float xr[4], xz[4], xn[4];
    const float* xgp[4];
    int hcidx[4];                              // fragment word index per p
#pragma unroll
    for (int p = 0; p < 4; p++) {
        int s = sblk + p * 4;
        int n = n0 + s;
        if (key < 3) {
            const float* xg = &g_xg012[(key * BV + n) * GG];
            xr[p] = xg[dd]; xz[p] = xg[DD + dd]; xn[p] = xg[2 * DD + dd];
            xgp[p] = nullptr;
        } else {
            xgp[p] = &g_xg34[(((key - 3) * BV + n) * MM) * GG];
        }
        int fl = (s & 7) * 4 + (dd & 3);                     // fragment lane
        int slot = (s >= 8 ? 1 : 0) + 2 * ((dd >> 2) & 1);
        hcidx[p] = (dd >> 3) * 128 + fl * 4 + slot;
    }

    int r = lane >> 2, cc = lane & 3;
    const uint2* Bb = s_wB + (wid * 3 * 16) * 32 + lane;   // 3 j-tiles per warp

    for (int t = 0; t < MM; t++) {
        if (key >= 3) {
#pragma unroll
            for (int p = 0; p < 4; p++) {
                const float* xg = xgp[p] + t * GG;
                xr[p] = __ldg(xg + dd);
                xz[p] = __ldg(xg + DD + dd);
                xn[p] = __ldg(xg + 2 * DD + dd);
            }
        }
        float c[3][4];
#pragma unroll
        for (int j = 0; j < 3; j++)
#pragma unroll
            for (int q = 0; q < 4; q++) c[j][q] = 0.f;
#pragma unroll 4
        for (int ks = 0; ks < 16; ks++) {
            uint4 A4 = *(const uint4*)&s_hc[ks * 128 + lane * 4];
            uint32_t A[4] = {A4.x, A4.y, A4.z, A4.w};
#pragma unroll
            for (int j = 0; j < 3; j++) {
                uint2 b = Bb[(j * 16 + ks) * 32];
                mma_tf32(c[j], A, b);
            }
        }
#pragma unroll
        for (int j = 0; j < 3; j++) {
            int col = wid * 24 + j * 8 + 2 * cc;
            *(float2*)&s_gh[r * 392 + col] = make_float2(c[j][0], c[j][1]);
            *(float2*)&s_gh[(r + 8) * 392 + col] = make_float2(c[j][2], c[j][3]);
        }
        __syncthreads();
#pragma unroll
        for (int p = 0; p < 4; p++) {
            int s = sblk + p * 4;
            float ghr = s_gh[s * 392 + dd];
            float ghz = s_gh[s * 392 + DD + dd];
            float ghn = s_gh[s * 392 + 2 * DD + dd];
            float rr = sigf(xr[p] + ghr + br);
            float zz = sigf(xz[p] + ghz + bz);
            float nn = tanhf_fast(xn[p] + rr * (ghn + bn));
            h[p] = (1.f - zz) * nn + zz * h[p];
            s_hc[hcidx[p]] = f2tf32(h[p]);
        }
        __syncthreads();
    }
#pragma unroll
    for (int p = 0; p < 4; p++) {
        int s = sblk + p * 4;
        g_h5[(key * BV + n0 + s) * DD + dd] = h[p];
    }
}

// ---------------- K5+K6 fused: visit input-gates + visit GRU recurrence -------
__global__ void __launch_bounds__(384) k_vxg_vis(
        const float* __restrict__ weight, const float* __restrict__ age,
        const float* __restrict__ info_w, const float* __restrict__ info_b,
        const float* __restrict__ bih, const float* __restrict__ bhh) {
    extern __shared__ float sm[];
    float* s_w  = sm;                   // 49152
    float* s_xg = sm + 49152;           // 6208
    float* s_h  = s_xg + 6208;          // 128
    float* s_gh = s_h + 128;            // 384
    float* sx   = s_xg;                 // alias (2048 floats) during phase 1-2
    int key = blockIdx.y, b = blockIdx.x, g = threadIdx.x;
    for (int i = g; i < 16 * DD; i += GG) {
        int v = i / DD, d = i % DD;
        float x;
        if (key < 5)       x = g_h5[(key * BV + b * 16 + v) * DD + d];
        else if (key == 5) x = weight[b * 16 + v] * info_w[d] + info_b[d];
        else               x = age[b * 16 + v] * info_w[DD + d] + info_b[DD + d];
        sx[i] = x;
    }
    __syncthreads();
    float bb = bih[key * GG + g];
    float acc[16];
#pragma unroll
    for (int v = 0; v < 16; v++) acc[v] = bb;
    {
        const float* w = &g_wT[WIH_V + key * (DD * GG) + g];
        for (int d = 0; d < DD; d++) {
            float wv = w[d * GG];
#pragma unroll
            for (int v = 0; v < 16; v++) acc[v] += wv * sx[v * DD + d];
        }
    }
    __syncthreads();
#pragma unroll
    for (int v = 0; v < 16; v++) s_xg[v * 388 + g] = acc[v];
    {
        const float4* src = (const float4*)&g_wT[WHH_V + key * (DD * GG)];
        float4* dst = (float4*)s_w;
        for (int i = g; i < 12288; i += GG) dst[i] = src[i];
    }
    if (g < DD) s_h[g] = 0.f;
    float bh = bhh[key * GG + g];
    __syncthreads();
    for (int t = 0; t < 16; t++) {
        float a = bh;
#pragma unroll 4
        for (int d = 0; d < DD; d++) a += s_w[d * GG + g] * s_h[d];
        s_gh[g] = a;
        __syncthreads();
        if (g < DD) {
            const float* xg = &s_xg[t * 388];
            float r = sigf(xg[g] + s_gh[g]);
            float z = sigf(xg[DD + g] + s_gh[DD + g]);
            float nn = tanhf_fast(xg[2 * DD + g] + r * s_gh[2 * DD + g]);
            s_h[g] = (1.f - z) * nn + z * s_h[g];
        }
        __syncthreads();
    }
    if (g < DD) g_hv[(key * 16 + b) * DD + g] = s_h[g];
}

// ---------------- K7: ReLU + final FC --------------------------------------------
__global__ void k_fc(const float* fcw, const float* fcb, float* out) {
    __shared__ float pe[7 * DD];
    int b = blockIdx.x, o = threadIdx.x;
    for (int i = o; i < 7 * DD; i += 256) {
        int k = i / DD, d = i % DD;
        pe[i] = fmaxf(g_hv[(k * 16 + b) * DD + d], 0.f);
    }
    __syncthreads();
    if (o < NOUT) {
        float acc = fcb[o];
        for (int j = 0; j < 7 * DD; j++) acc += pe[j] * fcw[j * NOUT + o];
        out[b * NOUT + o] = acc;
    }
}

// ---------------- launch -----------------------------------------------------------
extern "C" void kernel_launch(void* const* d_in, const int* in_sizes, int n_in,
                              void* d_out, int out_size) {
    const int* tok_cond      = (const int*)d_in[0];
    const int* tok_proc      = (const int*)d_in[1];
    const int* tok_drug      = (const int*)d_in[2];
    const int* tok_lab_item  = (const int*)d_in[3];
    const int* tok_lab_value = (const int*)d_in[4];
    const int* tok_inj_item  = (const int*)d_in[5];
    const int* tok_inj_value = (const int*)d_in[6];
    const float* weight      = (const float*)d_in[7];
    const float* age         = (const float*)d_in[8];
    const float* emb_cond    = (const float*)d_in[9];
    const float* emb_proc    = (const float*)d_in[10];
    const float* emb_drug    = (const float*)d_in[11];
    const float* emb_li      = (const float*)d_in[12];
    const float* emb_lv      = (const float*)d_in[13];
    const float* emb_ii      = (const float*)d_in[14];
    const float* emb_iv      = (const float*)d_in[15];
    const float* mgru_wih    = (const float*)d_in[16];
    const float* mgru_whh    = (const float*)d_in[17];
    const float* mgru_bih    = (const float*)d_in[18];
    const float* mgru_bhh    = (const float*)d_in[19];
    const float* vgru_wih    = (const float*)d_in[20];
    const float* vgru_whh    = (const float*)d_in[21];
    const float* vgru_bih    = (const float*)d_in[22];
    const float* vgru_bhh    = (const float*)d_in[23];
    const float* info_w      = (const float*)d_in[24];
    const float* info_b      = (const float*)d_in[25];
    const float* fc_w        = (const float*)d_in[26];
    const float* fc_b        = (const float*)d_in[27];
    float* out = (float*)d_out;

    cudaFuncSetAttribute(k_mon_gru, cudaFuncAttributeMaxDynamicSharedMemorySize, 229888);
    cudaFuncSetAttribute(k_vxg_vis, cudaFuncAttributeMaxDynamicSharedMemorySize, 223488);

    // Streams/events created ONCE on the first call (before the harness's
    // pre-capture baseline) and reused forever.
    static cudaStream_t sA = nullptr, sB = nullptr;
    static cudaEvent_t eF = nullptr, eA = nullptr, eB = nullptr;
    if (sA == nullptr) {
        cudaStreamCreateWithFlags(&sA, cudaStreamNonBlocking);
        cudaStreamCreateWithFlags(&sB, cudaStreamNonBlocking);
        cudaEventCreateWithFlags(&eF, cudaEventDisableTiming);
        cudaEventCreateWithFlags(&eA, cudaEventDisableTiming);
        cudaEventCreateWithFlags(&eB, cudaEventDisableTiming);
    }

    cudaEventRecord(eF, 0);
    cudaStreamWaitEvent(sA, eF, 0);

    // stream A: weight prep (transpose + tf32 packs)
    k_prep<<<3936, 256, 0, sA>>>(mgru_wih, mgru_whh, vgru_wih, vgru_whh);
    cudaEventRecord(eA, sA);

    // stream B: visit embeddings + xg for keys 0-2 (needs transposed WIH_M)
    cudaStreamWaitEvent(sB, eA, 0);
    k_embed_xg012<<<dim3(256, 3), 384, 0, sB>>>(tok_cond, tok_proc, tok_drug,
                                                emb_cond, emb_proc, emb_drug, mgru_bih);
    cudaEventRecord(eB, sB);

    // main stream: fused embed+xg34 -> mon_gru -> visit -> fc
    cudaStreamWaitEvent(0, eA, 0);
    k_xg34_mma<<<dim3(128, 2), 512>>>(tok_lab_item, tok_lab_value,
                                      tok_inj_item, tok_inj_value,
                                      emb_li, emb_lv, emb_ii, emb_iv, mgru_bih);
    cudaStreamWaitEvent(0, eB, 0);
    k_mon_gru<<<dim3(16, 5), 512, 229888>>>(mgru_bhh);
    k_vxg_vis<<<dim3(16, 7), 384, 223488>>>(weight, age, info_w, info_b,
                                            vgru_bih, vgru_bhh);
    k_fc<<<16, 256>>>(fc_w, fc_b, out);
}